// round 1
// baseline (speedup 1.0000x reference)
#include <cuda_runtime.h>

// Embed3D: out[n,l, p*40 + 2k + {0,1}] = {sin, cos}(x[n,l,1+p] * div_term[k])
// x: (NL, 4) fp32, div_term: 20 fp32, out: (NL, 120) fp32, NL = 64*8192.
//
// One thread per output float4 (30 per (n,l) row). blockDim=240 => the block's
// float4 stores are exactly contiguous: index = blockIdx.x*240 + threadIdx.x.

#define NL_PER_BLOCK 8
#define THREADS_PER_BLOCK (NL_PER_BLOCK * 30)   // 240

__global__ __launch_bounds__(THREADS_PER_BLOCK)
void embed3d_kernel(const float* __restrict__ x,
                    const float* __restrict__ div_term,
                    float* __restrict__ out,
                    int total_nl) {
    __shared__ float s_div[20];
    if (threadIdx.x < 20) s_div[threadIdx.x] = div_term[threadIdx.x];
    __syncthreads();

    const int tid = threadIdx.x;
    const int j   = tid % 30;                    // which float4 within the row
    const int nl  = blockIdx.x * NL_PER_BLOCK + tid / 30;
    if (nl >= total_nl) return;

    const int p = j / 10;                        // pos component 0..2
    const int q = j - p * 10;                    // pair group 0..9

    const float pos = __ldg(&x[nl * 4 + 1 + p]); // broadcast via L1
    const float a0 = pos * s_div[2 * q];
    const float a1 = pos * s_div[2 * q + 1];

    float4 r;
    __sincosf(a0, &r.x, &r.y);
    __sincosf(a1, &r.z, &r.w);

    // Global float4 index = nl*30 + j = blockIdx.x*240 + tid  (contiguous)
    reinterpret_cast<float4*>(out)[nl * 30 + j] = r;
}

extern "C" void kernel_launch(void* const* d_in, const int* in_sizes, int n_in,
                              void* d_out, int out_size) {
    const float* x        = (const float*)d_in[0];
    const float* div_term = (const float*)d_in[1];
    float* out            = (float*)d_out;

    const int total_nl = in_sizes[0] / 4;        // 64*8192 = 524288
    const int grid = (total_nl + NL_PER_BLOCK - 1) / NL_PER_BLOCK;

    embed3d_kernel<<<grid, THREADS_PER_BLOCK>>>(x, div_term, out, total_nl);
}

// round 3
// speedup vs baseline: 1.4768x; 1.4768x over previous
#include <cuda_runtime.h>

// Embed3D: out[nl, p*40 + 2k + {0,1}] = {sin, cos}(x[nl,1+p] * div_term[k])
// x: (NL,4) fp32, div_term: 20 fp32, out: (NL,120) fp32, NL = 64*8192 = 524288.
//
// blockDim = 480 = 15 full warps; 480/30 = 16 rows per "slice".
// Each thread owns float4 slot j = tid%30 in 4 rows (r, r+16, r+32, r+48),
// so one block covers 64 rows. Stores are contiguous STG.128 per slice:
// global float4 index = nl*30 + j. 4 independent compute/store chains per
// thread give the ILP the previous version lacked.

#define THREADS 480
#define ROWS_PER_SLICE 16
#define SLICES 4
#define ROWS_PER_BLOCK (ROWS_PER_SLICE * SLICES)   // 64

__global__ __launch_bounds__(THREADS)
void embed3d_kernel(const float* __restrict__ x,
                    const float* __restrict__ div_term,
                    float* __restrict__ out,
                    int total_nl) {
    const int tid = threadIdx.x;
    const int j   = tid % 30;          // float4 slot within a row
    const int r   = tid / 30;          // row within slice (0..15)

    const int p = j / 10;              // pos component 0..2
    const int q = j - p * 10;          // pair group 0..9

    const float d0 = __ldg(&div_term[2 * q]);
    const float d1 = __ldg(&div_term[2 * q + 1]);

    const int nl_base = blockIdx.x * ROWS_PER_BLOCK + r;

    float pos[SLICES];
#pragma unroll
    for (int s = 0; s < SLICES; s++) {
        const int nl = nl_base + s * ROWS_PER_SLICE;
        pos[s] = __ldg(&x[nl * 4 + 1 + p]);
    }

#pragma unroll
    for (int s = 0; s < SLICES; s++) {
        const int nl = nl_base + s * ROWS_PER_SLICE;
        float4 v;
        __sincosf(pos[s] * d0, &v.x, &v.y);
        __sincosf(pos[s] * d1, &v.z, &v.w);
        reinterpret_cast<float4*>(out)[nl * 30 + j] = v;
    }
}

extern "C" void kernel_launch(void* const* d_in, const int* in_sizes, int n_in,
                              void* d_out, int out_size) {
    const float* x        = (const float*)d_in[0];
    const float* div_term = (const float*)d_in[1];
    float* out            = (float*)d_out;

    const int total_nl = in_sizes[0] / 4;   // 524288, divisible by 64
    const int grid = total_nl / ROWS_PER_BLOCK;

    embed3d_kernel<<<grid, THREADS>>>(x, div_term, out, total_nl);
}

// round 4
// speedup vs baseline: 1.6491x; 1.1167x over previous
#include <cuda_runtime.h>

// Embed3D: out[nl, p*40 + 2k + {0,1}] = {sin, cos}(x[nl,1+p] * div_term[k])
// x: (NL,4) fp32, div_term: 20 fp32, out: (NL,120) fp32, NL = 64*8192 = 524288.
//
// blockDim = 480 = 15 full warps; 480/30 = 16 rows per slice; 8 slices per
// thread => 128 rows per block, grid = 4096. Stores are contiguous STG.128
// (global float4 index = nl*30 + j) and use .cs (evict-first) since the
// 252MB output stream has zero reuse in L2.

#define THREADS 480
#define ROWS_PER_SLICE 16
#define SLICES 8
#define ROWS_PER_BLOCK (ROWS_PER_SLICE * SLICES)   // 128

__device__ __forceinline__ void stg_cs_v4(float4* ptr, float4 v) {
    asm volatile("st.global.cs.v4.f32 [%0], {%1, %2, %3, %4};"
                 :: "l"(ptr), "f"(v.x), "f"(v.y), "f"(v.z), "f"(v.w)
                 : "memory");
}

__global__ __launch_bounds__(THREADS)
void embed3d_kernel(const float* __restrict__ x,
                    const float* __restrict__ div_term,
                    float* __restrict__ out,
                    int total_nl) {
    const int tid = threadIdx.x;
    const int j   = tid % 30;          // float4 slot within a row
    const int r   = tid / 30;          // row within slice (0..15)

    const int p = j / 10;              // pos component 0..2
    const int q = j - p * 10;          // pair group 0..9

    const float d0 = __ldg(&div_term[2 * q]);
    const float d1 = __ldg(&div_term[2 * q + 1]);

    const int nl_base = blockIdx.x * ROWS_PER_BLOCK + r;

    // Batch all pos loads up front: 8 independent LDGs in flight.
    float pos[SLICES];
#pragma unroll
    for (int s = 0; s < SLICES; s++) {
        const int nl = nl_base + s * ROWS_PER_SLICE;
        pos[s] = __ldg(&x[nl * 4 + 1 + p]);
    }

#pragma unroll
    for (int s = 0; s < SLICES; s++) {
        const int nl = nl_base + s * ROWS_PER_SLICE;
        float4 v;
        __sincosf(pos[s] * d0, &v.x, &v.y);
        __sincosf(pos[s] * d1, &v.z, &v.w);
        stg_cs_v4(reinterpret_cast<float4*>(out) + nl * 30 + j, v);
    }
}

extern "C" void kernel_launch(void* const* d_in, const int* in_sizes, int n_in,
                              void* d_out, int out_size) {
    const float* x        = (const float*)d_in[0];
    const float* div_term = (const float*)d_in[1];
    float* out            = (float*)d_out;

    const int total_nl = in_sizes[0] / 4;   // 524288, divisible by 128
    const int grid = total_nl / ROWS_PER_BLOCK;

    embed3d_kernel<<<grid, THREADS>>>(x, div_term, out, total_nl);
}